// round 10
// baseline (speedup 1.0000x reference)
#include <cuda_runtime.h>
#include <math.h>

#define BB 8
#define LL 8192
#define CCH 256
#define NN 512
#define KK 16
#define FMINF 1.17549435e-38f
#define NCAND 32
#define CH 32            // k per chunk
#define NCH 8            // chunks

// scratch (no allocations allowed)
__device__ float g_w[BB * NN];            // FTZ proto_weights
__device__ float g_pn2[NN];               // |p_n|^2
__device__ float g_qq[BB * LL];           // |q_l|^2
__device__ float g_Pz[NN * CCH];          // element-transposed P (fragment-ready)
__device__ float g_Qz[BB * LL * CCH];     // element-transposed Q (64MB static)

__device__ __forceinline__ float warp_maxf(float v) {
    #pragma unroll
    for (int o = 16; o; o >>= 1) v = fmaxf(v, __shfl_xor_sync(0xffffffffu, v, o));
    return v;
}
__device__ __forceinline__ float warp_sumf(float v) {
    #pragma unroll
    for (int o = 16; o; o >>= 1) v += __shfl_xor_sync(0xffffffffu, v, o);
    return v;
}
__device__ __forceinline__ double warp_sumd(double v) {
    #pragma unroll
    for (int o = 16; o; o >>= 1) v += __shfl_xor_sync(0xffffffffu, v, o);
    return v;
}

__device__ __forceinline__ void mma_tf32(float& c0, float& c1, float& c2, float& c3,
                                         float a0, float a1, float a2, float a3,
                                         float b0, float b1) {
    asm volatile(
        "mma.sync.aligned.m16n8k8.row.col.f32.tf32.tf32.f32 "
        "{%0,%1,%2,%3}, {%4,%5,%6,%7}, {%8,%9}, {%0,%1,%2,%3};"
        : "+f"(c0), "+f"(c1), "+f"(c2), "+f"(c3)
        : "r"(__float_as_uint(a0)), "r"(__float_as_uint(a1)),
          "r"(__float_as_uint(a2)), "r"(__float_as_uint(a3)),
          "r"(__float_as_uint(b0)), "r"(__float_as_uint(b1)));
}

__device__ __forceinline__ float dot8(const float4& qa, const float4& qb,
                                      const float4& pa, const float4& pb) {
    float s = 0.f;
    s = fmaf(qa.x, pa.x, s); s = fmaf(qa.y, pa.y, s);
    s = fmaf(qa.z, pa.z, s); s = fmaf(qa.w, pa.w, s);
    s = fmaf(qb.x, pb.x, s); s = fmaf(qb.y, pb.y, s);
    s = fmaf(qb.z, pb.z, s); s = fmaf(qb.w, pb.w, s);
    return s;
}

__device__ __forceinline__ void cpa16(void* dst, const void* src) {
    unsigned d = (unsigned)__cvta_generic_to_shared(dst);
    asm volatile("cp.async.ca.shared.global [%0], [%1], 16;"
                 :: "r"(d), "l"(src) : "memory");
}

// ---------------------------------------------------------------------------
// prep: per-batch FTZ proto weights
// ---------------------------------------------------------------------------
__global__ void prep_w_kernel(const float* __restrict__ P,
                              const float* __restrict__ gt) {
    int b = blockIdx.x;
    int tid = threadIdx.x;
    int lane = tid & 31, wid = tid >> 5;
    __shared__ double gsd[CCH];
    __shared__ float xs[NN];
    __shared__ float redf[256];
    __shared__ double redd[256];
    __shared__ float sXmax, sZw;

    if (tid < CCH) {
        double s = 0.0;
        #pragma unroll
        for (int k = 0; k < KK; k++) s += (double)gt[(b * KK + k) * CCH + tid];
        gsd[tid] = (double)__fdiv_rn((float)s, 16.0f);
    }
    __syncthreads();

    for (int n = wid; n < NN; n += 8) {
        const float4* pr4 = (const float4*)(P + n * CCH);
        float4 v0 = pr4[lane];
        float4 v1 = pr4[lane + 32];
        int c0 = lane * 4, c1 = 128 + lane * 4;
        double a = 0.0;
        a = fma((double)v0.x, gsd[c0 + 0], a);
        a = fma((double)v0.y, gsd[c0 + 1], a);
        a = fma((double)v0.z, gsd[c0 + 2], a);
        a = fma((double)v0.w, gsd[c0 + 3], a);
        a = fma((double)v1.x, gsd[c1 + 0], a);
        a = fma((double)v1.y, gsd[c1 + 1], a);
        a = fma((double)v1.z, gsd[c1 + 2], a);
        a = fma((double)v1.w, gsd[c1 + 3], a);
        a = warp_sumd(a);
        if (lane == 0) xs[n] = __fdiv_rn((float)a, 0.1f);
    }
    __syncthreads();

    {
        float m = -INFINITY;
        for (int n = tid; n < NN; n += blockDim.x) m = fmaxf(m, xs[n]);
        redf[tid] = m;
        __syncthreads();
        for (int s = 128; s; s >>= 1) {
            if (tid < s) redf[tid] = fmaxf(redf[tid], redf[tid + s]);
            __syncthreads();
        }
        if (tid == 0) sXmax = redf[0];
        __syncthreads();
    }
    float X = sXmax;

    {
        double z = 0.0;
        for (int n = tid; n < NN; n += blockDim.x) {
            float e = expf(__fsub_rn(xs[n], X));
            if (e >= FMINF) z += (double)e;
        }
        redd[tid] = z;
        __syncthreads();
        for (int s = 128; s; s >>= 1) {
            if (tid < s) redd[tid] += redd[tid + s];
            __syncthreads();
        }
        if (tid == 0) sZw = (float)redd[0];
        __syncthreads();
    }
    float Zw = sZw;

    for (int n = tid; n < NN; n += blockDim.x) {
        float e = expf(__fsub_rn(xs[n], X));
        if (e < FMINF) e = 0.f;
        float w = __fdiv_rn(e, Zw);
        if (w < FMINF) w = 0.f;
        g_w[b * NN + n] = w;
    }
}

// ---------------------------------------------------------------------------
// prep: P element-transpose (+ |p|^2). Word k of each 16-word group moves to
// position (k&3)*4 + (k>>2)  =>  LDS.128 at word q*4 yields k={q,q+4,q+8,q+12}.
// ---------------------------------------------------------------------------
__global__ void prep_pz_kernel(const float* __restrict__ P) {
    int lane = threadIdx.x & 31, wid = threadIdx.x >> 5;
    int row = blockIdx.x * 8 + wid;
    const float4* p4 = (const float4*)(P + (size_t)row * CCH);
    float4 v0 = p4[lane], v1 = p4[lane + 32];
    float s = dot8(v0, v1, v0, v1);
    s = warp_sumf(s);
    if (lane == 0) g_pn2[row] = s;

    float* dst = g_Pz + (size_t)row * CCH;
    int b0 = (lane >> 2) * 16 + (lane & 3);
    dst[b0 + 0] = v0.x; dst[b0 + 4] = v0.y; dst[b0 + 8] = v0.z; dst[b0 + 12] = v0.w;
    int b1 = ((lane >> 2) + 8) * 16 + (lane & 3);
    dst[b1 + 0] = v1.x; dst[b1 + 4] = v1.y; dst[b1 + 8] = v1.z; dst[b1 + 12] = v1.w;
}

// prep: Q element-transpose (+ |q|^2), same permutation, fused single pass
__global__ void prep_qz_kernel(const float* __restrict__ Q) {
    int lane = threadIdx.x & 31, wid = threadIdx.x >> 5;
    int row = blockIdx.x * 8 + wid;
    const float4* q4 = (const float4*)(Q + (size_t)row * CCH);
    float4 v0 = q4[lane], v1 = q4[lane + 32];
    float s = dot8(v0, v1, v0, v1);
    s = warp_sumf(s);
    if (lane == 0) g_qq[row] = s;

    float* dst = g_Qz + (size_t)row * CCH;
    int b0 = (lane >> 2) * 16 + (lane & 3);
    dst[b0 + 0] = v0.x; dst[b0 + 4] = v0.y; dst[b0 + 8] = v0.z; dst[b0 + 12] = v0.w;
    int b1 = ((lane >> 2) + 8) * 16 + (lane & 3);
    dst[b1 + 0] = v1.x; dst[b1 + 4] = v1.y; dst[b1 + 8] = v1.z; dst[b1 + 12] = v1.w;
}

// ---------------------------------------------------------------------------
// Main kernel: TF32 mma filter + exact refinement. cp.async double-buffered
// k=32 chunks, one barrier per chunk. Block = 64 rows x 512 protos, 512 thr
// (16 warps = 2 L-halves x 8 N-octants), warp = 32L x 64N.
// ---------------------------------------------------------------------------
struct __align__(16) SmemT {
    float pA[2][NN][16];     // k-half 0 of chunk, double-buffered (64 KB)
    float pB[2][NN][16];     // k-half 1 (64 KB)
    float qA[2][64][16];     // (8 KB)
    float qB[2][64][16];     // (8 KB)
    float wS[NN], pn2S[NN];
    float dmS[8][64];
    int   cnt[64];
    int   cand_n[64][NCAND];
    float candd[64][NCAND];
};

__global__ void __launch_bounds__(512, 1)
match_kernel(const float* __restrict__ Q, const float* __restrict__ P,
             float* __restrict__ out) {
    extern __shared__ char smem_raw[];
    SmemT& S = *(SmemT*)smem_raw;

    int tid = threadIdx.x;
    int lane = tid & 31, w = tid >> 5;
    int lh = w & 1;
    int nq = w >> 1;
    int g = lane >> 2, q = lane & 3;

    int R0 = blockIdx.x * 64;
    int b = R0 >> 13;

    if (tid < NN) {
        S.wS[tid] = g_w[b * NN + tid];
        S.pn2S[tid] = g_pn2[tid];
    }
    if (tid < 64) { S.cnt[tid] = 1; S.cand_n[tid][0] = 0; }

    const float* Qb = Q + (size_t)R0 * CCH;

    float acc[2][8][4];
    #pragma unroll
    for (int ms = 0; ms < 2; ms++)
        #pragma unroll
        for (int ns = 0; ns < 8; ns++)
            #pragma unroll
            for (int e = 0; e < 4; e++) acc[ms][ns][e] = 0.f;

    // async staging of one k=32 chunk into buffer t
    auto issue = [&](int c, int t) {
        #pragma unroll
        for (int r = 0; r < 8; r++) {
            int e = tid + r * 512;                 // 0..4095
            int n = e >> 3, h = (e >> 2) & 1, f = e & 3;
            const float* src = g_Pz + (size_t)n * CCH + c * CH + h * 16 + f * 4;
            float* dst = h ? &S.pB[t][n][f * 4] : &S.pA[t][n][f * 4];
            cpa16(dst, src);
        }
        {
            int l = tid >> 3, h = (tid >> 2) & 1, f = tid & 3;
            const float* src = g_Qz + (size_t)(R0 + l) * CCH + c * CH + h * 16 + f * 4;
            float* dst = h ? &S.qB[t][l][f * 4] : &S.qA[t][l][f * 4];
            cpa16(dst, src);
        }
        asm volatile("cp.async.commit_group;" ::: "memory");
    };

    issue(0, 0);
    for (int c = 0; c < NCH; c++) {
        asm volatile("cp.async.wait_group 0;" ::: "memory");
        __syncthreads();                           // buffer c ready; prior compute done
        if (c + 1 < NCH) issue(c + 1, (c + 1) & 1);
        int t = c & 1;

        #pragma unroll
        for (int m = 0; m < 2; m++) {              // two k16 macro-steps
            const float (*px)[16] = m ? S.pB[t] : S.pA[t];
            const float (*qx)[16] = m ? S.qB[t] : S.qA[t];
            float4 A[2][2];
            #pragma unroll
            for (int ms = 0; ms < 2; ms++)
                #pragma unroll
                for (int h = 0; h < 2; h++) {
                    int row = lh * 32 + ms * 16 + 8 * h + g;
                    A[ms][h] = *(const float4*)&qx[row][q * 4];
                }
            #pragma unroll
            for (int ns = 0; ns < 8; ns++) {
                int n = nq * 64 + ns * 8 + g;
                float4 Bv = *(const float4*)&px[n][q * 4];
                #pragma unroll
                for (int ms = 0; ms < 2; ms++) {
                    mma_tf32(acc[ms][ns][0], acc[ms][ns][1], acc[ms][ns][2], acc[ms][ns][3],
                             A[ms][0].x, A[ms][1].x, A[ms][0].y, A[ms][1].y, Bv.x, Bv.y);
                    mma_tf32(acc[ms][ns][0], acc[ms][ns][1], acc[ms][ns][2], acc[ms][ns][3],
                             A[ms][0].z, A[ms][1].z, A[ms][0].w, A[ms][1].w, Bv.z, Bv.w);
                }
            }
        }
    }
    __syncthreads();

    // ---- Phase 1: per-(octant,row) local max of approx dot ----
    #pragma unroll
    for (int ms = 0; ms < 2; ms++)
        #pragma unroll
        for (int h = 0; h < 2; h++) {
            int r = lh * 32 + ms * 16 + 8 * h + g;
            float vm = -INFINITY;
            #pragma unroll
            for (int ns = 0; ns < 8; ns++)
                #pragma unroll
                for (int e = 0; e < 2; e++)
                    vm = fmaxf(vm, acc[ms][ns][2 * h + e]);
            vm = fmaxf(vm, __shfl_xor_sync(0xffffffffu, vm, 1));
            vm = fmaxf(vm, __shfl_xor_sync(0xffffffffu, vm, 2));
            if (q == 0) S.dmS[nq][r] = vm;
        }
    __syncthreads();

    // ---- Phase 2: candidate push (approx dot within 9.4 of approx max) ----
    #pragma unroll
    for (int ms = 0; ms < 2; ms++)
        #pragma unroll
        for (int h = 0; h < 2; h++) {
            int r = lh * 32 + ms * 16 + 8 * h + g;
            float gdm = -INFINITY;
            #pragma unroll
            for (int o = 0; o < 8; o++) gdm = fmaxf(gdm, S.dmS[o][r]);
            float dthr = gdm - 9.4f;
            #pragma unroll
            for (int ns = 0; ns < 8; ns++)
                #pragma unroll
                for (int e = 0; e < 2; e++) {
                    float v = acc[ms][ns][2 * h + e];
                    int n = nq * 64 + ns * 8 + 2 * q + e;
                    if (n != 0 && v > dthr) {
                        int slot = atomicAdd(&S.cnt[r], 1);
                        if (slot < NCAND) S.cand_n[r][slot] = n;
                    }
                }
        }
    __syncthreads();

    // ---- Phase 3: owner warp refines 4 rows (exact f32; FTZ chain) ----
    #pragma unroll 1
    for (int rr = 0; rr < 4; rr++) {
        int r = w * 4 + rr;
        int cntr = S.cnt[r];
        const float4* q4 = (const float4*)(Qb + r * CCH);

        int bn = 0;
        float bp = 0.f;
        float bd;

        if (cntr <= NCAND) {
            int m = cntr;
            float4 qa = q4[lane], qb = q4[lane + 32];

            #pragma unroll 1
            for (int i0 = 0; i0 < m; i0 += 4) {
                int mm = min(4, m - i0);
                float4 pa[4], pb[4];
                #pragma unroll
                for (int j = 0; j < 4; j++)
                    if (j < mm) {
                        const float4* p4 =
                            (const float4*)(P + S.cand_n[r][i0 + j] * CCH);
                        pa[j] = p4[lane];
                        pb[j] = p4[lane + 32];
                    }
                float s[4];
                #pragma unroll
                for (int j = 0; j < 4; j++)
                    if (j < mm) s[j] = dot8(qa, qb, pa[j], pb[j]);
                #pragma unroll
                for (int o = 16; o; o >>= 1)
                    #pragma unroll
                    for (int j = 0; j < 4; j++)
                        if (j < mm) s[j] += __shfl_xor_sync(0xffffffffu, s[j], o);
                if (lane == 0)
                    #pragma unroll
                    for (int j = 0; j < 4; j++)
                        if (j < mm) S.candd[r][i0 + j] = s[j];
            }
            __syncwarp();

            float dmax = S.candd[r][0];
            for (int i = 1; i < m; i++) dmax = fmaxf(dmax, S.candd[r][i]);
            float Xf = __fdiv_rn(dmax, 0.1f);

            double z = 0.0;
            for (int i = 0; i < m; i++) {
                float x = __fdiv_rn(S.candd[r][i], 0.1f);
                float e = expf(__fsub_rn(x, Xf));
                if (e >= FMINF) z += (double)e;
            }
            float Za = (float)z;

            bd = S.candd[r][0];
            for (int i = 0; i < m; i++) {
                int n = S.cand_n[r][i];
                float d = S.candd[r][i];
                float x = __fdiv_rn(d, 0.1f);
                float e = expf(__fsub_rn(x, Xf));
                if (e < FMINF) e = 0.f;
                float sc = __fdiv_rn(e, Za);
                if (sc < FMINF) sc = 0.f;
                float p = __fmul_rn(sc, S.wS[n]);
                if (p < FMINF) p = 0.f;
                if (p > bp || (p == bp && p > 0.f && n < bn)) {
                    bp = p; bn = n; bd = d;
                }
            }
        } else {
            // overflow: full exact 512-proto scan (rare; always correct).
            // pA[0] is dead — column w (w<16) as per-warp dot scratch.
            #pragma unroll 1
            for (int n = 0; n < NN; n++) {
                const float4* p4 = (const float4*)(P + n * CCH);
                float s = warp_sumf(dot8(q4[lane], q4[lane + 32],
                                         p4[lane], p4[lane + 32]));
                if (lane == 0) S.pA[0][n][w] = s;
            }
            __syncwarp();
            float dmax = -INFINITY;
            for (int n = 0; n < NN; n++) dmax = fmaxf(dmax, S.pA[0][n][w]);
            float Xf = __fdiv_rn(dmax, 0.1f);
            double z = 0.0;
            for (int n = 0; n < NN; n++) {
                float x = __fdiv_rn(S.pA[0][n][w], 0.1f);
                float e = expf(__fsub_rn(x, Xf));
                if (e >= FMINF) z += (double)e;
            }
            float Za = (float)z;
            bd = S.pA[0][0][w];
            for (int n = 0; n < NN; n++) {
                float d = S.pA[0][n][w];
                float x = __fdiv_rn(d, 0.1f);
                float e = expf(__fsub_rn(x, Xf));
                if (e < FMINF) e = 0.f;
                float sc = __fdiv_rn(e, Za);
                if (sc < FMINF) sc = 0.f;
                float p = __fmul_rn(sc, S.wS[n]);
                if (p < FMINF) p = 0.f;
                if (p > bp) { bp = p; bn = n; bd = d; }
            }
        }

        if (lane == 0) {
            int row = R0 + r;
            out[row] = fmaf(-2.0f, bd, g_qq[row]) + S.pn2S[bn];
        }
    }
}

// ---------------------------------------------------------------------------
extern "C" void kernel_launch(void* const* d_in, const int* in_sizes, int n_in,
                              void* d_out, int out_size) {
    const float* Q = nullptr;
    const float* P = nullptr;
    const float* G = nullptr;
    for (int i = 0; i < n_in; i++) {
        if (in_sizes[i] == BB * LL * CCH) Q = (const float*)d_in[i];
        else if (in_sizes[i] == NN * CCH) P = (const float*)d_in[i];
        else if (in_sizes[i] == BB * KK * CCH) G = (const float*)d_in[i];
    }
    float* out = (float*)d_out;

    cudaFuncSetAttribute(match_kernel,
                         cudaFuncAttributeMaxDynamicSharedMemorySize,
                         (int)sizeof(SmemT));

    prep_w_kernel<<<BB, 256>>>(P, G);
    prep_pz_kernel<<<NN / 8, 256>>>(P);
    prep_qz_kernel<<<BB * LL / 8, 256>>>(Q);
    match_kernel<<<BB * LL / 64, 512, sizeof(SmemT)>>>(Q, P, out);
}